// round 2
// baseline (speedup 1.0000x reference)
#include <cuda_runtime.h>
#include <cstdint>

// Problem dims
#define Bq 256
#define Tq 512
#define Hq 256
#define H3 768
#define Mq (Bq * Tq)   // 131072

typedef unsigned long long ull;

// 402 MB scratch for the precomputed input projection GI = X@Wi + bi
__device__ float g_GI[(size_t)Mq * H3];

// ---------- f32x2 packed helpers (full-rate fp32 on sm_100) ----------
__device__ __forceinline__ void ffma2(ull& d, ull a, ull b) {
    asm("fma.rn.f32x2 %0, %1, %2, %0;" : "+l"(d) : "l"(a), "l"(b));
}
__device__ __forceinline__ ull pack2(float lo, float hi) {
    ull d;
    asm("mov.b64 %0, {%1, %2};" : "=l"(d) : "f"(lo), "f"(hi));
    return d;
}
__device__ __forceinline__ void unpack2(ull d, float& lo, float& hi) {
    asm("mov.b64 {%0, %1}, %2;" : "=f"(lo), "=f"(hi) : "l"(d));
}

// =====================================================================
// Phase 1: GI[m][n] = X[m][:] @ Wi[:][n] + bi[n]
// M=131072, N=768, K=256.  128x128x16 tiles, 256 threads, 8x8/thread.
// =====================================================================
__global__ __launch_bounds__(256) void gi_gemm(const float* __restrict__ X,
                                               const float* __restrict__ Wi,
                                               const float* __restrict__ bi) {
    __shared__ __align__(16) float As[16][128];   // k-major (transposed A)
    __shared__ __align__(16) float Bs[16][128];
    const int tid = threadIdx.x;
    const int tx = tid & 15;       // col group (8 cols)
    const int ty = tid >> 4;       // row group (8 rows)
    const int m0 = blockIdx.y * 128;
    const int n0 = blockIdx.x * 128;

    ull acc[8][4];
#pragma unroll
    for (int r = 0; r < 8; r++)
#pragma unroll
        for (int c = 0; c < 4; c++) acc[r][c] = 0ULL;

    for (int k0 = 0; k0 < Hq; k0 += 16) {
        // Load A tile: 128 rows x 16 k, transpose into As[k][row]
#pragma unroll
        for (int i = 0; i < 2; i++) {
            int lid = tid + i * 256;
            int row = lid >> 2;           // 0..127
            int kq  = (lid & 3) * 4;      // 0,4,8,12
            float4 v = *(const float4*)(X + (size_t)(m0 + row) * Hq + k0 + kq);
            As[kq + 0][row] = v.x;
            As[kq + 1][row] = v.y;
            As[kq + 2][row] = v.z;
            As[kq + 3][row] = v.w;
        }
        // Load B tile: 16 k-rows x 128 cols
#pragma unroll
        for (int i = 0; i < 2; i++) {
            int lid = tid + i * 256;
            int kr = lid >> 5;            // 0..15
            int cq = (lid & 31) * 4;
            *(float4*)&Bs[kr][cq] =
                *(const float4*)(Wi + (size_t)(k0 + kr) * H3 + n0 + cq);
        }
        __syncthreads();

#pragma unroll
        for (int k = 0; k < 16; k++) {
            ulonglong2 b01 = *(const ulonglong2*)&Bs[k][tx * 8];
            ulonglong2 b23 = *(const ulonglong2*)&Bs[k][tx * 8 + 4];
            ull bb[4] = {b01.x, b01.y, b23.x, b23.y};
            float4 a0 = *(const float4*)&As[k][ty * 8];
            float4 a1 = *(const float4*)&As[k][ty * 8 + 4];
            float av[8] = {a0.x, a0.y, a0.z, a0.w, a1.x, a1.y, a1.z, a1.w};
#pragma unroll
            for (int r = 0; r < 8; r++) {
                ull ad = pack2(av[r], av[r]);
#pragma unroll
                for (int c = 0; c < 4; c++) ffma2(acc[r][c], ad, bb[c]);
            }
        }
        __syncthreads();
    }

    // Epilogue: add bias, store
    float bv[8];
#pragma unroll
    for (int c = 0; c < 8; c++) bv[c] = bi[n0 + tx * 8 + c];
#pragma unroll
    for (int r = 0; r < 8; r++) {
        float out[8];
#pragma unroll
        for (int c = 0; c < 4; c++) {
            float lo, hi;
            unpack2(acc[r][c], lo, hi);
            out[2 * c]     = lo + bv[2 * c];
            out[2 * c + 1] = hi + bv[2 * c + 1];
        }
        float* dst = g_GI + (size_t)(m0 + ty * 8 + r) * H3 + n0 + tx * 8;
        *(float4*)dst       = make_float4(out[0], out[1], out[2], out[3]);
        *(float4*)(dst + 4) = make_float4(out[4], out[5], out[6], out[7]);
    }
}

// =====================================================================
// Phase 2: sequential GRU scan. 64 blocks x 4 batches, 384 threads.
// Each thread owns 2 adjacent gh columns; h carry lives in SMEM as
// duplicated f32x2 pairs so the inner loop is LDG.64 + LDS.128 + FMA2.
// Wh (786 KB) is read by all 64 blocks every step -> L2-resident.
// =====================================================================
__global__ __launch_bounds__(384) void recur_kernel(
    const float* __restrict__ Wh, const float* __restrict__ bn,
    const int* __restrict__ resets, const float* __restrict__ h0,
    float* __restrict__ ys, float* __restrict__ hT) {
    __shared__ __align__(16) float hdup[4][2 * Hq];  // [b][2j]=[b][2j+1]=h[b][j]
    __shared__ float gh[4][H3];
    __shared__ float bns[Hq];
    __shared__ int rst[4];

    const int t  = threadIdx.x;      // 0..383
    const int b0 = blockIdx.x * 4;

    for (int i = t; i < Hq; i += 384) bns[i] = bn[i];
    for (int i = t; i < 4 * Hq; i += 384) {
        int b = i >> 8, j = i & 255;
        float v = h0[(size_t)(b0 + b) * Hq + j];
        hdup[b][2 * j] = v;
        hdup[b][2 * j + 1] = v;
    }
    __syncthreads();

    const float* wp = Wh + 2 * t;

    for (int s = 0; s < Tq; s++) {
        if (t < 4) rst[t] = resets[(size_t)(b0 + t) * Tq + s];
        __syncthreads();

        // reset carry where flagged (BEFORE the cell runs)
        for (int i = t; i < 4 * Hq; i += 384) {
            int b = i >> 8, j = i & 255;
            if (rst[b]) { hdup[b][2 * j] = 0.f; hdup[b][2 * j + 1] = 0.f; }
        }
        __syncthreads();

        // gh[b][c] = sum_k h[b][k] * Wh[k][c] for this thread's 2 columns
        ull acc0 = 0ULL, acc1 = 0ULL, acc2 = 0ULL, acc3 = 0ULL;
        const ulonglong2* h0v = (const ulonglong2*)hdup[0];
        const ulonglong2* h1v = (const ulonglong2*)hdup[1];
        const ulonglong2* h2v = (const ulonglong2*)hdup[2];
        const ulonglong2* h3v = (const ulonglong2*)hdup[3];
#pragma unroll 4
        for (int k2 = 0; k2 < Hq / 2; k2++) {
            ull w0 = *(const ull*)(wp + (size_t)(2 * k2) * H3);
            ull w1 = *(const ull*)(wp + (size_t)(2 * k2 + 1) * H3);
            ulonglong2 hb0 = h0v[k2];
            ulonglong2 hb1 = h1v[k2];
            ulonglong2 hb2 = h2v[k2];
            ulonglong2 hb3 = h3v[k2];
            ffma2(acc0, w0, hb0.x); ffma2(acc0, w1, hb0.y);
            ffma2(acc1, w0, hb1.x); ffma2(acc1, w1, hb1.y);
            ffma2(acc2, w0, hb2.x); ffma2(acc2, w1, hb2.y);
            ffma2(acc3, w0, hb3.x); ffma2(acc3, w1, hb3.y);
        }
        {
            float lo, hi;
            unpack2(acc0, lo, hi); *(float2*)&gh[0][2 * t] = make_float2(lo, hi);
            unpack2(acc1, lo, hi); *(float2*)&gh[1][2 * t] = make_float2(lo, hi);
            unpack2(acc2, lo, hi); *(float2*)&gh[2][2 * t] = make_float2(lo, hi);
            unpack2(acc3, lo, hi); *(float2*)&gh[3][2 * t] = make_float2(lo, hi);
        }
        __syncthreads();

        // Elementwise gates + carry update + output store
        for (int i = t; i < 4 * Hq; i += 384) {
            int b = i >> 8, j = i & 255;
            size_t m = (size_t)(b0 + b) * Tq + s;
            const float* gi = g_GI + m * H3;
            float ir = gi[j], iz = gi[j + 256], in_ = gi[j + 512];
            float hr = gh[b][j], hz = gh[b][j + 256], hn = gh[b][j + 512];
            float hold = hdup[b][2 * j];
            float r = 1.f / (1.f + __expf(-(ir + hr)));
            float z = 1.f / (1.f + __expf(-(iz + hz)));
            float n = tanhf(in_ + r * (hn + bns[j]));
            float nh = (1.f - z) * n + z * hold;
            ys[m * Hq + j] = nh;
            hdup[b][2 * j] = nh;
            hdup[b][2 * j + 1] = nh;
        }
        __syncthreads();
    }

    if (hT != nullptr) {
        for (int i = t; i < 4 * Hq; i += 384) {
            int b = i >> 8, j = i & 255;
            hT[(size_t)(b0 + b) * Hq + j] = hdup[b][2 * j];
        }
    }
}

// =====================================================================
// kernel_launch
// Inputs (metadata order): x, resets, Wi, bi, Wh, bn, h0
// Output: flattened (hT [B,H], ys [B,T,H]) tuple — hT first; if out_size
// only covers ys, write ys alone.
// =====================================================================
extern "C" void kernel_launch(void* const* d_in, const int* in_sizes, int n_in,
                              void* d_out, int out_size) {
    (void)in_sizes; (void)n_in;
    const float* x      = (const float*)d_in[0];
    const int*   resets = (const int*)d_in[1];
    const float* Wi     = (const float*)d_in[2];
    const float* bi     = (const float*)d_in[3];
    const float* Wh     = (const float*)d_in[4];
    const float* bn     = (const float*)d_in[5];
    const float* h0     = (const float*)d_in[6];
    float* out = (float*)d_out;

    const size_t ys_elems = (size_t)Bq * Tq * Hq;       // 33554432
    const size_t ht_elems = (size_t)Bq * Hq;            // 65536
    float* hT;
    float* ys;
    if ((size_t)out_size >= ys_elems + ht_elems) {
        hT = out;
        ys = out + ht_elems;
    } else {
        hT = nullptr;
        ys = out;
    }

    // Phase 1: input projection GEMM into scratch
    dim3 g1(H3 / 128, Mq / 128);   // (6, 1024)
    gi_gemm<<<g1, 256>>>(x, Wi, bi);

    // Phase 2: sequential scan (stream-ordered after the GEMM)
    recur_kernel<<<Bq / 4, 384>>>(Wh, bn, resets, h0, ys, hT);
}

// round 3
// speedup vs baseline: 1.6776x; 1.6776x over previous
#include <cuda_runtime.h>
#include <cstdint>

// Problem dims
#define Bq 256
#define Tq 512
#define Hq 256
#define H3 768
#define Mq (Bq * Tq)   // 131072

// Persistent-kernel partitioning: 16 col-groups x 8 batch-groups = 128 blocks
#define NCG 16
#define NBG 8
#define NBLK 128
#define JPG 16          // j columns per col-group
#define BPG 32          // batches per batch-group
#define PTHREADS 384

typedef unsigned long long ull;

// Scratch: input projection GI = X@Wi + bi (402 MB), h carry ping buffer, barrier
__device__ float g_GI[(size_t)Mq * H3];
__device__ float g_h[(size_t)Bq * Hq];
__device__ unsigned g_ctr;

// ---------- f32x2 packed helpers ----------
__device__ __forceinline__ void ffma2(ull& d, ull a, ull b) {
    asm("fma.rn.f32x2 %0, %1, %2, %0;" : "+l"(d) : "l"(a), "l"(b));
}
__device__ __forceinline__ ull addf2(ull a, ull b) {
    ull d;
    asm("add.rn.f32x2 %0, %1, %2;" : "=l"(d) : "l"(a), "l"(b));
    return d;
}
__device__ __forceinline__ ull pack2(float lo, float hi) {
    ull d;
    asm("mov.b64 %0, {%1, %2};" : "=l"(d) : "f"(lo), "f"(hi));
    return d;
}
__device__ __forceinline__ void unpack2(ull d, float& lo, float& hi) {
    asm("mov.b64 {%0, %1}, %2;" : "=f"(lo), "=f"(hi) : "l"(d));
}
__device__ __forceinline__ float sigf(float x) {
    float e, r;
    asm("ex2.approx.f32 %0, %1;" : "=f"(e) : "f"(-1.4426950408889634f * x));
    asm("rcp.approx.f32 %0, %1;" : "=f"(r) : "f"(1.0f + e));
    return r;
}
__device__ __forceinline__ float tanh_acc(float x) {
    // tanh(x) = 2*sigmoid(2x) - 1 : keeps error at MUFU-approx level (~1e-7)
    return 2.0f * sigf(2.0f * x) - 1.0f;
}

// =====================================================================
// Phase 1: GI[m][n] = X[m][:] @ Wi[:][n] + bi[n]
// M=131072, N=768, K=256.  128x128x16 tiles, 256 threads, 8x8/thread.
// =====================================================================
__global__ __launch_bounds__(256) void gi_gemm(const float* __restrict__ X,
                                               const float* __restrict__ Wi,
                                               const float* __restrict__ bi) {
    __shared__ __align__(16) float As[16][128];
    __shared__ __align__(16) float Bs[16][128];
    const int tid = threadIdx.x;
    const int tx = tid & 15;
    const int ty = tid >> 4;
    const int m0 = blockIdx.y * 128;
    const int n0 = blockIdx.x * 128;

    ull acc[8][4];
#pragma unroll
    for (int r = 0; r < 8; r++)
#pragma unroll
        for (int c = 0; c < 4; c++) acc[r][c] = 0ULL;

    for (int k0 = 0; k0 < Hq; k0 += 16) {
#pragma unroll
        for (int i = 0; i < 2; i++) {
            int lid = tid + i * 256;
            int row = lid >> 2;
            int kq = (lid & 3) * 4;
            float4 v = *(const float4*)(X + (size_t)(m0 + row) * Hq + k0 + kq);
            As[kq + 0][row] = v.x;
            As[kq + 1][row] = v.y;
            As[kq + 2][row] = v.z;
            As[kq + 3][row] = v.w;
        }
#pragma unroll
        for (int i = 0; i < 2; i++) {
            int lid = tid + i * 256;
            int kr = lid >> 5;
            int cq = (lid & 31) * 4;
            *(float4*)&Bs[kr][cq] =
                *(const float4*)(Wi + (size_t)(k0 + kr) * H3 + n0 + cq);
        }
        __syncthreads();

#pragma unroll
        for (int k = 0; k < 16; k++) {
            ulonglong2 b01 = *(const ulonglong2*)&Bs[k][tx * 8];
            ulonglong2 b23 = *(const ulonglong2*)&Bs[k][tx * 8 + 4];
            ull bb[4] = {b01.x, b01.y, b23.x, b23.y};
            float4 a0 = *(const float4*)&As[k][ty * 8];
            float4 a1 = *(const float4*)&As[k][ty * 8 + 4];
            float av[8] = {a0.x, a0.y, a0.z, a0.w, a1.x, a1.y, a1.z, a1.w};
#pragma unroll
            for (int r = 0; r < 8; r++) {
                ull ad = pack2(av[r], av[r]);
#pragma unroll
                for (int c = 0; c < 4; c++) ffma2(acc[r][c], ad, bb[c]);
            }
        }
        __syncthreads();
    }

    float bv[8];
#pragma unroll
    for (int c = 0; c < 8; c++) bv[c] = bi[n0 + tx * 8 + c];
#pragma unroll
    for (int r = 0; r < 8; r++) {
        float out[8];
#pragma unroll
        for (int c = 0; c < 4; c++) {
            float lo, hi;
            unpack2(acc[r][c], lo, hi);
            out[2 * c] = lo + bv[2 * c];
            out[2 * c + 1] = hi + bv[2 * c + 1];
        }
        float* dst = g_GI + (size_t)(m0 + ty * 8 + r) * H3 + n0 + tx * 8;
        *(float4*)dst = make_float4(out[0], out[1], out[2], out[3]);
        *(float4*)(dst + 4) = make_float4(out[4], out[5], out[6], out[7]);
    }
}

// =====================================================================
// init: h carry = reset-masked h0, zero the barrier counter
// =====================================================================
__global__ void init_h(const int* __restrict__ resets, const float* __restrict__ h0) {
    int idx = blockIdx.x * blockDim.x + threadIdx.x;
    if (idx == 0) g_ctr = 0u;
    if (idx < Bq * Hq) {
        int b = idx >> 8;
        g_h[idx] = resets[(size_t)b * Tq] ? 0.0f : h0[idx];
    }
}

// =====================================================================
// Phase 2: persistent GRU scan with per-step grid barrier.
// Block (cg, bg) owns j in [cg*16, cg*16+16) and batches [bg*32, bg*32+32).
// Wh slice (48 cols: {j, j+256, j+512}) lives in SMEM for all 512 steps.
// SMEM layout (dynamic):
//   Whs  float[256][48]       49152 B   @ 0
//   Hd   ull  [32][256]       65536 B   @ 49152   (dup-packed {h,h} per k)
//   Ghf  float[48][33]         6336 B   @ 114688  (padded: bank-conflict-free)
//   Part ull  [4][24][32]     24576 B   @ 121024  (k-quarter partial sums)
//   Bns  float[16]               64 B   @ 145600
// total 145664 B
// =====================================================================
#define SM_WHS 0
#define SM_HD 49152
#define SM_GHF 114688
#define SM_PART 121024
#define SM_BNS 145600
#define SM_TOTAL 145664

__global__ __launch_bounds__(PTHREADS, 1) void gru_persist(
    const float* __restrict__ Wh, const float* __restrict__ bn,
    const int* __restrict__ resets, float* __restrict__ ys,
    float* __restrict__ hT) {
    extern __shared__ __align__(16) char smem[];
    float* Whs = (float*)(smem + SM_WHS);        // [k][48]
    ull* Hd = (ull*)(smem + SM_HD);              // [b_loc][k]
    float* Ghf = (float*)(smem + SM_GHF);        // [c][33]
    ull* Part = (ull*)(smem + SM_PART);          // [kq][cp][b_loc]
    float* Bns = (float*)(smem + SM_BNS);

    const int tid = threadIdx.x;
    const int cg = blockIdx.x & 15;
    const int bg = blockIdx.x >> 4;
    const int j0 = cg * JPG;
    const int b0 = bg * BPG;

    // dot-product role
    const int co = tid % 6;          // col-oct: 8 cols at co*8
    const int gq = (tid / 6) % 16;   // batch pair: b_loc {2gq, 2gq+1}
    const int kq = tid / 96;         // k-quarter: k in [kq*64, kq*64+64)

    // One-time: load Wh slice + bn slice into SMEM
    for (int idx = tid; idx < 256 * 48; idx += PTHREADS) {
        int k = idx / 48, c = idx % 48;
        int gate = c >> 4, jj = c & 15;
        Whs[idx] = Wh[(size_t)k * H3 + gate * Hq + j0 + jj];
    }
    if (tid < JPG) Bns[tid] = bn[j0 + tid];

    for (int s = 0; s < Tq; s++) {
        // ---- prefetch gi + next-reset for this step's gate phase ----
        float pir[2], piz[2], pin[2];
        int prst[2];
#pragma unroll
        for (int u = 0; u < 2; u++) {
            int i = tid + u * PTHREADS;
            if (i < 512) {
                int b = b0 + (i >> 4);
                int j = j0 + (i & 15);
                size_t m = (size_t)b * Tq + s;
                const float* gp = g_GI + m * H3;
                pir[u] = __ldcg(gp + j);
                piz[u] = __ldcg(gp + Hq + j);
                pin[u] = __ldcg(gp + 2 * Hq + j);
                prst[u] = (s < Tq - 1) ? __ldcg(resets + (size_t)b * Tq + s + 1) : 0;
            }
        }

        // ---- load h slice (post-reset values, written by previous step) ----
        for (int i = tid; i < (BPG * Hq) / 4; i += PTHREADS) {
            int b_loc = i >> 6;
            int k4 = (i & 63) << 2;
            float4 v = __ldcg((const float4*)(g_h + (size_t)(b0 + b_loc) * Hq + k4));
            ull* dst = &Hd[b_loc * 256 + k4];
            dst[0] = pack2(v.x, v.x);
            dst[1] = pack2(v.y, v.y);
            dst[2] = pack2(v.z, v.z);
            dst[3] = pack2(v.w, v.w);
        }
        __syncthreads();

        // ---- dot: gh[c][b] partials over this thread's k-quarter ----
        ull a00 = 0, a10 = 0, a20 = 0, a30 = 0;
        ull a01 = 0, a11 = 0, a21 = 0, a31 = 0;
        {
            const float* wp = &Whs[(kq * 64) * 48 + co * 8];
            const ull* h0p = &Hd[(2 * gq) * 256 + kq * 64];
            const ull* h1p = &Hd[(2 * gq + 1) * 256 + kq * 64];
#pragma unroll 4
            for (int k = 0; k < 64; k++) {
                ulonglong2 wA = *(const ulonglong2*)(wp);
                ulonglong2 wB = *(const ulonglong2*)(wp + 4);
                ull hd0 = h0p[k];
                ull hd1 = h1p[k];
                ffma2(a00, wA.x, hd0); ffma2(a10, wA.y, hd0);
                ffma2(a20, wB.x, hd0); ffma2(a30, wB.y, hd0);
                ffma2(a01, wA.x, hd1); ffma2(a11, wA.y, hd1);
                ffma2(a21, wB.x, hd1); ffma2(a31, wB.y, hd1);
                wp += 48;
            }
        }
        {
            ull* P = &Part[(size_t)(kq * 24 + co * 4) * 32];
            int bA = 2 * gq, bB = 2 * gq + 1;
            P[0 * 32 + bA] = a00; P[0 * 32 + bB] = a01;
            P[1 * 32 + bA] = a10; P[1 * 32 + bB] = a11;
            P[2 * 32 + bA] = a20; P[2 * 32 + bB] = a21;
            P[3 * 32 + bA] = a30; P[3 * 32 + bB] = a31;
        }
        __syncthreads();

        // ---- reduce 4 k-quarters -> Ghf ----
        for (int idx = tid; idx < 768; idx += PTHREADS) {
            int cp = idx >> 5, b = idx & 31;
            ull sum = addf2(addf2(Part[(0 * 24 + cp) * 32 + b], Part[(1 * 24 + cp) * 32 + b]),
                            addf2(Part[(2 * 24 + cp) * 32 + b], Part[(3 * 24 + cp) * 32 + b]));
            float lo, hi;
            unpack2(sum, lo, hi);
            Ghf[(2 * cp) * 33 + b] = lo;
            Ghf[(2 * cp + 1) * 33 + b] = hi;
        }
        __syncthreads();

        // ---- gates + carry update + output ----
#pragma unroll
        for (int u = 0; u < 2; u++) {
            int i = tid + u * PTHREADS;
            if (i < 512) {
                int jl = i & 15, bl = i >> 4;
                int b = b0 + bl, j = j0 + jl;
                float hr = Ghf[jl * 33 + bl];
                float hz = Ghf[(16 + jl) * 33 + bl];
                float hn = Ghf[(32 + jl) * 33 + bl];
                float hold;
                {
                    float lo, hi;
                    unpack2(Hd[bl * 256 + j], lo, hi);
                    hold = lo; (void)hi;
                }
                float r = sigf(pir[u] + hr);
                float z = sigf(piz[u] + hz);
                float n = tanh_acc(pin[u] + r * (hn + Bns[jl]));
                float nh = (1.0f - z) * n + z * hold;
                size_t m = (size_t)b * Tq + s;
                ys[m * Hq + j] = nh;
                g_h[(size_t)b * Hq + j] = prst[u] ? 0.0f : nh;
                if (s == Tq - 1 && hT != nullptr) hT[(size_t)b * Hq + j] = nh;
            }
        }

        // ---- grid barrier ----
        __syncthreads();
        if (tid == 0) {
            __threadfence();
            atomicAdd(&g_ctr, 1u);
            unsigned target = (unsigned)NBLK * (unsigned)(s + 1);
            while (*(volatile unsigned*)&g_ctr < target) __nanosleep(64);
            __threadfence();
        }
        __syncthreads();
    }
}

// =====================================================================
// kernel_launch — inputs: x, resets, Wi, bi, Wh, bn, h0
// =====================================================================
extern "C" void kernel_launch(void* const* d_in, const int* in_sizes, int n_in,
                              void* d_out, int out_size) {
    (void)in_sizes; (void)n_in;
    const float* x      = (const float*)d_in[0];
    const int*   resets = (const int*)d_in[1];
    const float* Wi     = (const float*)d_in[2];
    const float* bi     = (const float*)d_in[3];
    const float* Wh     = (const float*)d_in[4];
    const float* bn     = (const float*)d_in[5];
    const float* h0     = (const float*)d_in[6];
    float* out = (float*)d_out;

    const size_t ys_elems = (size_t)Bq * Tq * Hq;
    const size_t ht_elems = (size_t)Bq * Hq;
    float* hT;
    float* ys;
    if ((size_t)out_size >= ys_elems + ht_elems) {
        hT = out;
        ys = out + ht_elems;
    } else {
        hT = nullptr;
        ys = out;
    }

    static bool attr_done = false;
    if (!attr_done) {
        cudaFuncSetAttribute(gru_persist, cudaFuncAttributeMaxDynamicSharedMemorySize,
                             SM_TOTAL);
        attr_done = true;
    }

    dim3 g1(H3 / 128, Mq / 128);
    gi_gemm<<<g1, 256>>>(x, Wi, bi);
    init_h<<<(Bq * Hq + 255) / 256, 256>>>(resets, h0);
    gru_persist<<<NBLK, PTHREADS, SM_TOTAL>>>(Wh, bn, resets, ys, hT);
}